// round 15
// baseline (speedup 1.0000x reference)
#include <cuda_runtime.h>
#include <cuda_fp16.h>

typedef unsigned int u32;

static constexpr int NPTS  = 1048576;
static constexpr int TPB   = 256;
static constexpr int TILE_PTS = 256;
static constexpr int TILES = NPTS / TILE_PTS;  // 4096
static constexpr int NBLK  = 444;              // 3 CTAs/SM * 148 SMs

// fp16 staging: per warp, 3 planes x 16 rows x 20 u32 (one 16-pt chunk)
static constexpr int SF_U32_PER_WARP = 3 * 16 * 20;            // 960
static constexpr int SF_BYTES = 8 * SF_U32_PER_WARP * 4;       // 30720
static constexpr int N2 = 100;                                 // all frags uint2 (hi-only)
static constexpr int SWF2_OFF = SF_BYTES;                      // 30720
static constexpr int SMEM_TOTAL = SWF2_OFF + N2 * 256;         // 56320

// frag index map in swf2:
//  W1  (96,64): 0..47   (kt*8+nt)
//  W3' (16,64): 48..55  (nt)
//  W4  (64,64): 56..87  (kt*8+nt)
//  W5' (64,8):  88..91  (kt)
//  W2  (64,16): 92..99  (kt*2+nt)

// ---------------- planes as fp16 u-paired cells ----------------
// g2[q][v][u] = 64 halves: [c][s], s=0 -> plane(c,v,u), s=1 -> plane(c,v,min(u+1,255))
__device__ __half g2[3 * 256 * 256 * 64];

__global__ void transpose_kernel(const float* __restrict__ pxy,
                                 const float* __restrict__ pxz,
                                 const float* __restrict__ pyz) {
    __shared__ float tile[32][33];
    const float* src = blockIdx.z == 0 ? pxy : (blockIdx.z == 1 ? pxz : pyz);
    const int x0 = blockIdx.x * 32;
    const int y  = blockIdx.y;
    const int tx = threadIdx.x;
    const int ty = threadIdx.y;

    tile[ty][tx] = src[ty * 65536 + y * 256 + x0 + tx];
    if (tx == 0) {
        const int ulast = min(x0 + 32, 255);
        tile[ty][32] = src[ty * 65536 + y * 256 + ulast];
    }
    __syncthreads();

    const float a = tile[tx][ty];
    const float b = tile[tx][ty + 1];
    half2 hp = __floats2half2_rn(a, b);
    u32* g2u = (u32*)g2;
    g2u[((u32)blockIdx.z * 65536u + (u32)(y * 256 + x0 + ty)) * 32u + (u32)tx] =
        *reinterpret_cast<u32*>(&hp);
}

// ---------------- helpers ----------------
__device__ __forceinline__ u32 hi2(float a, float b) {
    half2 h = __floats2half2_rn(a, b);
    return *reinterpret_cast<u32*>(&h);
}

__device__ __forceinline__ void mma16(float* d, const u32* a, u32 b0, u32 b1) {
    asm volatile("mma.sync.aligned.m16n8k16.row.col.f32.f16.f16.f32 "
                 "{%0,%1,%2,%3}, {%4,%5,%6,%7}, {%8,%9}, {%0,%1,%2,%3};"
                 : "+f"(d[0]), "+f"(d[1]), "+f"(d[2]), "+f"(d[3])
                 : "r"(a[0]), "r"(a[1]), "r"(a[2]), "r"(a[3]), "r"(b0), "r"(b1));
}

__device__ __forceinline__ void build_hi_relu(const float* s0, const float* s1, u32* ah) {
    ah[0] = hi2(fmaxf(s0[0], 0.f), fmaxf(s0[1], 0.f));
    ah[1] = hi2(fmaxf(s0[2], 0.f), fmaxf(s0[3], 0.f));
    ah[2] = hi2(fmaxf(s1[0], 0.f), fmaxf(s1[1], 0.f));
    ah[3] = hi2(fmaxf(s1[2], 0.f), fmaxf(s1[3], 0.f));
}
__device__ __forceinline__ void build_hi(const float* s0, const float* s1, u32* ah) {
    ah[0] = hi2(s0[0], s0[1]);
    ah[1] = hi2(s0[2], s0[3]);
    ah[2] = hi2(s1[0], s1[1]);
    ah[3] = hi2(s1[2], s1[3]);
}

__device__ __forceinline__ float sigm(float x) { return 1.f / (1.f + __expf(-x)); }

__global__ __launch_bounds__(TPB, 3)
void nerf_mma(const float* __restrict__ xin,
              const float* __restrict__ center,
              const float* __restrict__ scale,
              const float* __restrict__ w1,
              const float* __restrict__ w2,
              const float* __restrict__ w3,
              const float* __restrict__ w4,
              const float* __restrict__ w5,
              float* __restrict__ out) {
    extern __shared__ __align__(16) char smem[];
    u32*   sf16 = (u32*)smem;
    uint2* swf2 = (uint2*)(smem + SWF2_OFF);

    const int tid  = threadIdx.x;
    const int wid  = tid >> 5;
    const int lane = tid & 31;
    const int g  = lane >> 2;        // fragment row group
    const int t2 = (lane & 3) * 2;   // fragment col pair

    // ---- build weight fragments (all hi-only uint2) ----
    for (int f = wid; f < 100; f += 8) {
        float v0, v1, v2, v3;
        int idx;
        if (f < 48) {
            int kt = f >> 3, nt = f & 7;
            int ka = kt * 16 + t2, n = nt * 8 + g;
            v0 = w1[ka * 64 + n];       v1 = w1[(ka + 1) * 64 + n];
            v2 = w1[(ka + 8) * 64 + n]; v3 = w1[(ka + 9) * 64 + n];
            idx = f;
        } else if (f < 56) {
            int q = f - 48, kt = q >> 1, nt = q & 1;
            int ka = kt * 16 + t2, n = nt * 8 + g;
            v0 = w2[ka * 16 + n];       v1 = w2[(ka + 1) * 16 + n];
            v2 = w2[(ka + 8) * 16 + n]; v3 = w2[(ka + 9) * 16 + n];
            idx = 92 + q;
        } else if (f < 64) {
            int nt = f - 56;
            int ka = t2, n = nt * 8 + g;
            v0 = (ka == 0) ? 0.f : w3[(ka - 1) * 64 + n];
            v1 = w3[ka * 64 + n];
            v2 = w3[(ka + 7) * 64 + n];
            v3 = w3[(ka + 8) * 64 + n];
            idx = 48 + nt;
        } else if (f < 96) {
            int q = f - 64, kt = q >> 3, nt = q & 7;
            int ka = kt * 16 + t2, n = nt * 8 + g;
            v0 = w4[ka * 64 + n];       v1 = w4[(ka + 1) * 64 + n];
            v2 = w4[(ka + 8) * 64 + n]; v3 = w4[(ka + 9) * 64 + n];
            idx = 56 + q;
        } else {
            int kt = f - 96;
            int ka = kt * 16 + t2, n = g;
            v0 = (n < 3) ? w5[ka * 3 + n] : 0.f;
            v1 = (n < 3) ? w5[(ka + 1) * 3 + n] : 0.f;
            v2 = (n < 3) ? w5[(ka + 8) * 3 + n] : 0.f;
            v3 = (n < 3) ? w5[(ka + 9) * 3 + n] : 0.f;
            idx = 88 + kt;
        }
        uint2 q2;
        q2.x = hi2(v0, v1);
        q2.y = hi2(v2, v3);
        swf2[idx * 32 + lane] = q2;
    }
    __syncthreads();

    const float c0 = center[0], c1 = center[1], c2 = center[2];
    const float s0 = scale[0],  s1 = scale[1],  s2 = scale[2];
    const int jj = lane & 7;     // channel chunk (4 channels)
    const int p4 = lane >> 3;    // point-in-group
    const int wb = wid * SF_U32_PER_WARP;   // staging base (u32)
    const int cb = lane & 3;     // u32 col within k-tile

    for (int tile = blockIdx.x; tile < TILES; tile += gridDim.x) {
        const int pid = tile * TILE_PTS + wid * 32 + lane;
        const float px = xin[3 * pid + 0];
        const float py = xin[3 * pid + 1];
        const float pz = xin[3 * pid + 2];

        float vx = fminf(fmaxf((px - c0) / s0 + 0.5f, 0.f), 1.f) * 255.f;
        float vy = fminf(fmaxf((py - c1) / s1 + 0.5f, 0.f), 1.f) * 255.f;
        float vz = fminf(fmaxf((pz - c2) / s2 + 0.5f, 0.f), 1.f) * 255.f;
        float flx = floorf(vx), fly = floorf(vy), flz = floorf(vz);
        float fx = vx - flx, fy = vy - fly, fz = vz - flz;
        int x0i = (int)flx;
        int y0i = (int)fly, y1i = min(y0i + 1, 255);
        int z0i = (int)flz, z1i = min(z0i + 1, 255);

        // per-lane geometry for this lane's point (3 planes)
        u32 gm[3];
        float gfu[3], gfv[3];
        {
            const float fus[3] = {fx, fx, fy};
            const float fvs[3] = {fy, fz, fz};
            const int u0s[3] = {x0i, x0i, y0i};
            const int v0s[3] = {y0i, z0i, z0i}, v1s[3] = {y1i, z1i, z1i};
#pragma unroll
            for (int q = 0; q < 3; q++) {
                u32 base = ((u32)q * 65536u + (u32)(v0s[q] * 256 + u0s[q])) * 64u;
                gm[q] = base | ((v1s[q] > v0s[q]) ? (1u << 31) : 0u);
                gfu[q] = fus[q];
                gfv[q] = fvs[q];
            }
        }

        // ---- two 16-pt chunks, fully unpaired pipeline ----
#pragma unroll
        for (int c = 0; c < 2; c++) {
            __syncwarp();   // previous chunk's staging reads done

            // gather this chunk: 12 rounds, 2 LDG each
#pragma unroll
            for (int q = 0; q < 3; q++) {
#pragma unroll
                for (int gq = 0; gq < 4; gq++) {
                    const int src = c * 16 + gq * 4 + p4;
                    u32 meta = __shfl_sync(0xffffffffu, gm[q], src);
                    float fu = __shfl_sync(0xffffffffu, gfu[q], src);
                    float fv = __shfl_sync(0xffffffffu, gfv[q], src);
                    const __half* cell = g2 + (meta & 0x00FFFFFFu) + (u32)(jj * 8);
                    u32 dv = (meta >> 31) * 16384u;
                    float4 rv0 = *(const float4*)cell;
                    float4 rv1 = *(const float4*)(cell + dv);
                    const half2* h0 = (const half2*)&rv0;
                    const half2* h1 = (const half2*)&rv1;
                    const float wu1 = fu, wu0 = 1.f - fu;
                    float res[4];
#pragma unroll
                    for (int i = 0; i < 4; i++) {
                        float2 a = __half22float2(h0[i]);
                        float2 b = __half22float2(h1[i]);
                        float r0 = a.x * wu0 + a.y * wu1;
                        float r1 = b.x * wu0 + b.y * wu1;
                        res[i] = r0 + (r1 - r0) * fv;
                    }
                    uint2 hp;
                    hp.x = hi2(res[0], res[1]);
                    hp.y = hi2(res[2], res[3]);
                    *(uint2*)&sf16[wb + q * 320 + (gq * 4 + p4) * 20 + jj * 2] = hp;
                }
            }
            __syncwarp();

            // ---- L1 (1-term) ----
            float D1[8][4];
#pragma unroll
            for (int n = 0; n < 8; n++)
#pragma unroll
                for (int q = 0; q < 4; q++) D1[n][q] = 0.f;
#pragma unroll
            for (int kt = 0; kt < 6; kt++) {
                const int q = kt >> 1, kq = kt & 1;
                const int base = wb + q * 320;
                const int col = kq * 8 + cb;
                u32 A0[4];
                A0[0] = sf16[base + g * 20 + col];
                A0[1] = sf16[base + (g + 8) * 20 + col];
                A0[2] = sf16[base + g * 20 + col + 4];
                A0[3] = sf16[base + (g + 8) * 20 + col + 4];
#pragma unroll
                for (int nt = 0; nt < 8; nt++) {
                    uint2 B = swf2[(kt * 8 + nt) * 32 + lane];
                    mma16(D1[nt], A0, B.x, B.y);
                }
            }

            // ---- L2 (1-term) ----
            float D2[2][4];
#pragma unroll
            for (int n = 0; n < 2; n++)
#pragma unroll
                for (int q = 0; q < 4; q++) D2[n][q] = 0.f;
#pragma unroll
            for (int kt = 0; kt < 4; kt++) {
                u32 ah[4];
                build_hi_relu(D1[2 * kt], D1[2 * kt + 1], ah);
#pragma unroll
                for (int nt = 0; nt < 2; nt++) {
                    uint2 B = swf2[(92 + kt * 2 + nt) * 32 + lane];
                    mma16(D2[nt], ah, B.x, B.y);
                }
            }
            const float sg0 = D2[0][0], sg1 = D2[0][2];

            // ---- L3 (1-term) ----
            float D3[8][4];
#pragma unroll
            for (int n = 0; n < 8; n++)
#pragma unroll
                for (int q = 0; q < 4; q++) D3[n][q] = 0.f;
            {
                u32 ah[4];
                build_hi(D2[0], D2[1], ah);
#pragma unroll
                for (int nt = 0; nt < 8; nt++) {
                    uint2 B = swf2[(48 + nt) * 32 + lane];
                    mma16(D3[nt], ah, B.x, B.y);
                }
            }

            // D3 -> hi-only A4 (in place register-wise)
            u32 A4[4][4];
#pragma unroll
            for (int kt = 0; kt < 4; kt++)
                build_hi_relu(D3[2 * kt], D3[2 * kt + 1], A4[kt]);

            // ---- L4 + L5, two n-halves ----
            float D5[4] = {0.f, 0.f, 0.f, 0.f};
#pragma unroll
            for (int half = 0; half < 2; half++) {
                float D4[4][4];
#pragma unroll
                for (int n = 0; n < 4; n++)
#pragma unroll
                    for (int q = 0; q < 4; q++) D4[n][q] = 0.f;
#pragma unroll
                for (int kt = 0; kt < 4; kt++) {
#pragma unroll
                    for (int nt = 0; nt < 4; nt++) {
                        uint2 B = swf2[(56 + kt * 8 + half * 4 + nt) * 32 + lane];
                        mma16(D4[nt], A4[kt], B.x, B.y);
                    }
                }
#pragma unroll
                for (int k5 = 0; k5 < 2; k5++) {
                    uint2 B = swf2[(88 + half * 2 + k5) * 32 + lane];
                    u32 ah[4];
                    build_hi_relu(D4[2 * k5], D4[2 * k5 + 1], ah);
                    mma16(D5, ah, B.x, B.y);
                }
            }

            // ---- epilogue ----
            const int lm = lane & 3;
            const int r0 = tile * TILE_PTS + wid * 32 + c * 16 + g;
            const int r1 = r0 + 8;
            if (lm == 0) {
                out[3 * r0 + 0] = sigm(D5[0]);
                out[3 * r0 + 1] = sigm(D5[1]);
                out[3 * r1 + 0] = sigm(D5[2]);
                out[3 * r1 + 1] = sigm(D5[3]);
                out[3 * NPTS + r0] = sg0;
                out[3 * NPTS + r1] = sg1;
            } else if (lm == 1) {
                out[3 * r0 + 2] = sigm(D5[0]);
                out[3 * r1 + 2] = sigm(D5[2]);
            }
        }
    }
}

extern "C" void kernel_launch(void* const* d_in, const int* in_sizes, int n_in,
                              void* d_out, int out_size) {
    const float* x      = (const float*)d_in[0];
    const float* pxy    = (const float*)d_in[2];
    const float* pxz    = (const float*)d_in[3];
    const float* pyz    = (const float*)d_in[4];
    const float* center = (const float*)d_in[5];
    const float* scale  = (const float*)d_in[6];
    const float* w1     = (const float*)d_in[7];
    const float* w2     = (const float*)d_in[8];
    const float* w3     = (const float*)d_in[9];
    const float* w4     = (const float*)d_in[10];
    const float* w5     = (const float*)d_in[11];

    cudaFuncSetAttribute(nerf_mma, cudaFuncAttributeMaxDynamicSharedMemorySize, SMEM_TOTAL);

    dim3 tb(32, 32), tg(8, 256, 3);
    transpose_kernel<<<tg, tb>>>(pxy, pxz, pyz);
    nerf_mma<<<NBLK, TPB, SMEM_TOTAL>>>(x, center, scale, w1, w2, w3, w4, w5, (float*)d_out);
}

// round 16
// speedup vs baseline: 1.1246x; 1.1246x over previous
#include <cuda_runtime.h>
#include <cuda_fp16.h>

typedef unsigned int u32;

static constexpr int NPTS  = 1048576;
static constexpr int TPB   = 256;
static constexpr int TILE_PTS = 256;
static constexpr int TILES = NPTS / TILE_PTS;  // 4096
static constexpr int NBLK  = 296;              // 2 CTAs/SM * 148 SMs

// fp16 staging: per warp, 3 planes x 32 rows x 20 u32 (16 data + 4 pad)
static constexpr int SF_U32_PER_WARP = 3 * 32 * 20;            // 1920
static constexpr int SF_BYTES = 8 * SF_U32_PER_WARP * 4;       // 61440
static constexpr int N2 = 100;                                 // all frags uint2 (hi-only)
static constexpr int SWF2_OFF = SF_BYTES;                      // 61440
static constexpr int SMEM_TOTAL = SWF2_OFF + N2 * 256;         // 87040

// frag index map in swf2:
//  W1  (96,64): 0..47   (kt*8+nt)
//  W3' (16,64): 48..55  (nt)
//  W4  (64,64): 56..87  (kt*8+nt)
//  W5' (64,8):  88..91  (kt)
//  W2  (64,16): 92..99  (kt*2+nt)

// ---------------- planes as fp16 u-paired cells ----------------
// g2[q][v][u] = 64 halves: [c][s], s=0 -> plane(c,v,u), s=1 -> plane(c,v,min(u+1,255))
__device__ __half g2[3 * 256 * 256 * 64];

__global__ void transpose_kernel(const float* __restrict__ pxy,
                                 const float* __restrict__ pxz,
                                 const float* __restrict__ pyz) {
    __shared__ float tile[32][33];
    const float* src = blockIdx.z == 0 ? pxy : (blockIdx.z == 1 ? pxz : pyz);
    const int x0 = blockIdx.x * 32;
    const int y  = blockIdx.y;
    const int tx = threadIdx.x;
    const int ty = threadIdx.y;

    tile[ty][tx] = src[ty * 65536 + y * 256 + x0 + tx];
    if (tx == 0) {
        const int ulast = min(x0 + 32, 255);
        tile[ty][32] = src[ty * 65536 + y * 256 + ulast];
    }
    __syncthreads();

    const float a = tile[tx][ty];
    const float b = tile[tx][ty + 1];
    half2 hp = __floats2half2_rn(a, b);
    u32* g2u = (u32*)g2;
    g2u[((u32)blockIdx.z * 65536u + (u32)(y * 256 + x0 + ty)) * 32u + (u32)tx] =
        *reinterpret_cast<u32*>(&hp);
}

// ---------------- helpers ----------------
__device__ __forceinline__ u32 hi2(float a, float b) {
    half2 h = __floats2half2_rn(a, b);
    return *reinterpret_cast<u32*>(&h);
}
// pack-then-relu: bitwise-equivalent to relu-then-pack (rounding is monotone,
// sign-preserving); 2 ops instead of 3.
__device__ __forceinline__ u32 hi2_relu(float a, float b) {
    half2 h = __floats2half2_rn(a, b);
    half2 z = __float2half2_rn(0.f);
    h = __hmax2(h, z);
    return *reinterpret_cast<u32*>(&h);
}

__device__ __forceinline__ void mma16(float* d, const u32* a, u32 b0, u32 b1) {
    asm volatile("mma.sync.aligned.m16n8k16.row.col.f32.f16.f16.f32 "
                 "{%0,%1,%2,%3}, {%4,%5,%6,%7}, {%8,%9}, {%0,%1,%2,%3};"
                 : "+f"(d[0]), "+f"(d[1]), "+f"(d[2]), "+f"(d[3])
                 : "r"(a[0]), "r"(a[1]), "r"(a[2]), "r"(a[3]), "r"(b0), "r"(b1));
}

__device__ __forceinline__ void build_hi_relu(const float* s0, const float* s1, u32* ah) {
    ah[0] = hi2_relu(s0[0], s0[1]);
    ah[1] = hi2_relu(s0[2], s0[3]);
    ah[2] = hi2_relu(s1[0], s1[1]);
    ah[3] = hi2_relu(s1[2], s1[3]);
}
__device__ __forceinline__ void build_hi(const float* s0, const float* s1, u32* ah) {
    ah[0] = hi2(s0[0], s0[1]);
    ah[1] = hi2(s0[2], s0[3]);
    ah[2] = hi2(s1[0], s1[1]);
    ah[3] = hi2(s1[2], s1[3]);
}

__device__ __forceinline__ float sigm(float x) { return 1.f / (1.f + __expf(-x)); }

__global__ __launch_bounds__(TPB, 2)
void nerf_mma(const float* __restrict__ xin,
              const float* __restrict__ center,
              const float* __restrict__ scale,
              const float* __restrict__ w1,
              const float* __restrict__ w2,
              const float* __restrict__ w3,
              const float* __restrict__ w4,
              const float* __restrict__ w5,
              float* __restrict__ out) {
    extern __shared__ __align__(16) char smem[];
    u32*   sf16 = (u32*)smem;
    uint2* swf2 = (uint2*)(smem + SWF2_OFF);

    const int tid  = threadIdx.x;
    const int wid  = tid >> 5;
    const int lane = tid & 31;
    const int g  = lane >> 2;        // fragment row group
    const int t2 = (lane & 3) * 2;   // fragment col pair

    // ---- build weight fragments (all hi-only uint2) ----
    for (int f = wid; f < 100; f += 8) {
        float v0, v1, v2, v3;
        int idx;
        if (f < 48) {
            int kt = f >> 3, nt = f & 7;
            int ka = kt * 16 + t2, n = nt * 8 + g;
            v0 = w1[ka * 64 + n];       v1 = w1[(ka + 1) * 64 + n];
            v2 = w1[(ka + 8) * 64 + n]; v3 = w1[(ka + 9) * 64 + n];
            idx = f;
        } else if (f < 56) {
            int q = f - 48, kt = q >> 1, nt = q & 1;
            int ka = kt * 16 + t2, n = nt * 8 + g;
            v0 = w2[ka * 16 + n];       v1 = w2[(ka + 1) * 16 + n];
            v2 = w2[(ka + 8) * 16 + n]; v3 = w2[(ka + 9) * 16 + n];
            idx = 92 + q;
        } else if (f < 64) {
            int nt = f - 56;
            int ka = t2, n = nt * 8 + g;
            v0 = (ka == 0) ? 0.f : w3[(ka - 1) * 64 + n];
            v1 = w3[ka * 64 + n];
            v2 = w3[(ka + 7) * 64 + n];
            v3 = w3[(ka + 8) * 64 + n];
            idx = 48 + nt;
        } else if (f < 96) {
            int q = f - 64, kt = q >> 3, nt = q & 7;
            int ka = kt * 16 + t2, n = nt * 8 + g;
            v0 = w4[ka * 64 + n];       v1 = w4[(ka + 1) * 64 + n];
            v2 = w4[(ka + 8) * 64 + n]; v3 = w4[(ka + 9) * 64 + n];
            idx = 56 + q;
        } else {
            int kt = f - 96;
            int ka = kt * 16 + t2, n = g;
            v0 = (n < 3) ? w5[ka * 3 + n] : 0.f;
            v1 = (n < 3) ? w5[(ka + 1) * 3 + n] : 0.f;
            v2 = (n < 3) ? w5[(ka + 8) * 3 + n] : 0.f;
            v3 = (n < 3) ? w5[(ka + 9) * 3 + n] : 0.f;
            idx = 88 + kt;
        }
        uint2 q2;
        q2.x = hi2(v0, v1);
        q2.y = hi2(v2, v3);
        swf2[idx * 32 + lane] = q2;
    }
    __syncthreads();

    const float c0 = center[0], c1 = center[1], c2 = center[2];
    const float s0 = scale[0],  s1 = scale[1],  s2 = scale[2];
    const int jj = lane & 7;     // channel chunk (4 channels)
    const int p4 = lane >> 3;    // point-in-group
    const int wb = wid * SF_U32_PER_WARP;   // staging base (u32)
    const int cb = lane & 3;     // u32 col within k-tile
    const half2 one2 = __float2half2_rn(1.f);

    for (int tile = blockIdx.x; tile < TILES; tile += gridDim.x) {
        const int pid = tile * TILE_PTS + wid * 32 + lane;
        const float px = xin[3 * pid + 0];
        const float py = xin[3 * pid + 1];
        const float pz = xin[3 * pid + 2];

        float vx = fminf(fmaxf((px - c0) / s0 + 0.5f, 0.f), 1.f) * 255.f;
        float vy = fminf(fmaxf((py - c1) / s1 + 0.5f, 0.f), 1.f) * 255.f;
        float vz = fminf(fmaxf((pz - c2) / s2 + 0.5f, 0.f), 1.f) * 255.f;
        float flx = floorf(vx), fly = floorf(vy), flz = floorf(vz);
        float fx = vx - flx, fy = vy - fly, fz = vz - flz;
        int x0i = (int)flx;
        int y0i = (int)fly, y1i = min(y0i + 1, 255);
        int z0i = (int)flz, z1i = min(z0i + 1, 255);

        // per-lane geometry: u-clamp baked into the cell layout; only v-flag needed
        u32 gm[3];
        float gfu[3], gfv[3];
        {
            const float fus[3] = {fx, fx, fy};
            const float fvs[3] = {fy, fz, fz};
            const int u0s[3] = {x0i, x0i, y0i};
            const int v0s[3] = {y0i, z0i, z0i}, v1s[3] = {y1i, z1i, z1i};
#pragma unroll
            for (int q = 0; q < 3; q++) {
                u32 base = ((u32)q * 65536u + (u32)(v0s[q] * 256 + u0s[q])) * 64u;
                gm[q] = base | ((v1s[q] > v0s[q]) ? (1u << 31) : 0u);
                gfu[q] = fus[q];
                gfv[q] = fvs[q];
            }
        }

        // ---- single-phase gather: 2 LDG per 4-point round; half2 lerp + PRMT pack ----
        __syncwarp();   // protect prior tile's staging reads
#pragma unroll
        for (int q = 0; q < 3; q++) {
#pragma unroll
            for (int gq = 0; gq < 8; gq++) {
                const int src = gq * 4 + p4;
                u32 meta = __shfl_sync(0xffffffffu, gm[q], src);
                float fu = __shfl_sync(0xffffffffu, gfu[q], src);
                float fv = __shfl_sync(0xffffffffu, gfv[q], src);
                const __half* cell = g2 + (meta & 0x00FFFFFFu) + (u32)(jj * 8);
                u32 dv = (meta >> 31) * 16384u;   // +256 cells * 64 halves
                float4 rv0 = *(const float4*)cell;
                float4 rv1 = *(const float4*)(cell + dv);
                const half2* h0 = (const half2*)&rv0;
                const half2* h1 = (const half2*)&rv1;
                const half2 fv2  = __float2half2_rn(fv);
                const half2 wu1h = __float2half2_rn(fu);
                const half2 wu0h = __hsub2(one2, wu1h);
                // v-lerp in fp16: hv[i] = h0 + (h1-h0)*fv  (channels 4jj..4jj+3, slots u0/u1)
                u32 hv[4];
#pragma unroll
                for (int i = 0; i < 4; i++) {
                    half2 t = __hfma2(__hsub2(h1[i], h0[i]), fv2, h0[i]);
                    hv[i] = *reinterpret_cast<u32*>(&t);
                }
                // repack to (u0 of c_even,c_odd) / (u1 of c_even,c_odd), then u-lerp
                u32 lo0 = __byte_perm(hv[0], hv[1], 0x5410);
                u32 hi0 = __byte_perm(hv[0], hv[1], 0x7632);
                u32 lo1 = __byte_perm(hv[2], hv[3], 0x5410);
                u32 hi1 = __byte_perm(hv[2], hv[3], 0x7632);
                half2 r0 = __hfma2(*reinterpret_cast<half2*>(&hi0), wu1h,
                                   __hmul2(*reinterpret_cast<half2*>(&lo0), wu0h));
                half2 r1 = __hfma2(*reinterpret_cast<half2*>(&hi1), wu1h,
                                   __hmul2(*reinterpret_cast<half2*>(&lo1), wu0h));
                uint2 hp;
                hp.x = *reinterpret_cast<u32*>(&r0);
                hp.y = *reinterpret_cast<u32*>(&r1);
                *(uint2*)&sf16[wb + q * 640 + (gq * 4 + p4) * 20 + jj * 2] = hp;
            }
        }
        __syncwarp();

        // ---- L1 paired: A exact fp16 (scalar LDS), B hi-only (1-term) ----
        float D1a[8][4], D1b[8][4];
#pragma unroll
        for (int n = 0; n < 8; n++)
#pragma unroll
            for (int q = 0; q < 4; q++) { D1a[n][q] = 0.f; D1b[n][q] = 0.f; }
#pragma unroll
        for (int kt = 0; kt < 6; kt++) {
            const int q = kt >> 1, kq = kt & 1;
            const int base = wb + q * 640;
            const int col = kq * 8 + cb;
            u32 A0[4], A1[4];
            A0[0] = sf16[base + g * 20 + col];
            A0[1] = sf16[base + (g + 8) * 20 + col];
            A0[2] = sf16[base + g * 20 + col + 4];
            A0[3] = sf16[base + (g + 8) * 20 + col + 4];
            A1[0] = sf16[base + (16 + g) * 20 + col];
            A1[1] = sf16[base + (24 + g) * 20 + col];
            A1[2] = sf16[base + (16 + g) * 20 + col + 4];
            A1[3] = sf16[base + (24 + g) * 20 + col + 4];
#pragma unroll
            for (int nt = 0; nt < 8; nt++) {
                uint2 B = swf2[(kt * 8 + nt) * 32 + lane];
                mma16(D1a[nt], A0, B.x, B.y);
                mma16(D1b[nt], A1, B.x, B.y);
            }
        }

        // ---- L2 paired (1-term) ----
        float D2a[2][4], D2b[2][4];
#pragma unroll
        for (int n = 0; n < 2; n++)
#pragma unroll
            for (int q = 0; q < 4; q++) { D2a[n][q] = 0.f; D2b[n][q] = 0.f; }
#pragma unroll
        for (int kt = 0; kt < 4; kt++) {
            u32 ahA[4], ahB[4];
            build_hi_relu(D1a[2 * kt], D1a[2 * kt + 1], ahA);
            build_hi_relu(D1b[2 * kt], D1b[2 * kt + 1], ahB);
#pragma unroll
            for (int nt = 0; nt < 2; nt++) {
                uint2 B = swf2[(92 + kt * 2 + nt) * 32 + lane];
                mma16(D2a[nt], ahA, B.x, B.y);
                mma16(D2b[nt], ahB, B.x, B.y);
            }
        }
        const float sgA0 = D2a[0][0], sgA1 = D2a[0][2];
        const float sgB0 = D2b[0][0], sgB1 = D2b[0][2];

        // ---- L3 paired (1-term, color path) ----
        float D3a[8][4], D3b[8][4];
#pragma unroll
        for (int n = 0; n < 8; n++)
#pragma unroll
            for (int q = 0; q < 4; q++) { D3a[n][q] = 0.f; D3b[n][q] = 0.f; }
        {
            u32 ahA[4], ahB[4];
            build_hi(D2a[0], D2a[1], ahA);
            build_hi(D2b[0], D2b[1], ahB);
#pragma unroll
            for (int nt = 0; nt < 8; nt++) {
                uint2 B = swf2[(48 + nt) * 32 + lane];
                mma16(D3a[nt], ahA, B.x, B.y);
                mma16(D3b[nt], ahB, B.x, B.y);
            }
        }

        // ---- D3 -> hi-only A4 ----
        u32 A4a[4][4], A4b[4][4];
#pragma unroll
        for (int kt = 0; kt < 4; kt++) {
            build_hi_relu(D3a[2 * kt], D3a[2 * kt + 1], A4a[kt]);
            build_hi_relu(D3b[2 * kt], D3b[2 * kt + 1], A4b[kt]);
        }

        // ---- L4 + L5 paired, 1-term, two n-halves ----
        float D5a[4] = {0.f, 0.f, 0.f, 0.f};
        float D5b[4] = {0.f, 0.f, 0.f, 0.f};
#pragma unroll
        for (int half = 0; half < 2; half++) {
            float D4a[4][4], D4b[4][4];
#pragma unroll
            for (int n = 0; n < 4; n++)
#pragma unroll
                for (int q = 0; q < 4; q++) { D4a[n][q] = 0.f; D4b[n][q] = 0.f; }
#pragma unroll
            for (int kt = 0; kt < 4; kt++) {
#pragma unroll
                for (int nt = 0; nt < 4; nt++) {
                    uint2 B = swf2[(56 + kt * 8 + half * 4 + nt) * 32 + lane];
                    mma16(D4a[nt], A4a[kt], B.x, B.y);
                    mma16(D4b[nt], A4b[kt], B.x, B.y);
                }
            }
#pragma unroll
            for (int k5 = 0; k5 < 2; k5++) {
                uint2 B = swf2[(88 + half * 2 + k5) * 32 + lane];
                u32 ah[4];
                build_hi_relu(D4a[2 * k5], D4a[2 * k5 + 1], ah);
                mma16(D5a, ah, B.x, B.y);
                build_hi_relu(D4b[2 * k5], D4b[2 * k5 + 1], ah);
                mma16(D5b, ah, B.x, B.y);
            }
        }

        // ---- epilogue ----
        const int lm = lane & 3;
        const int base0 = tile * TILE_PTS + wid * 32 + g;
#pragma unroll
        for (int c = 0; c < 2; c++) {
            const float* D5 = c == 0 ? D5a : D5b;
            const float sg0 = c == 0 ? sgA0 : sgB0;
            const float sg1 = c == 0 ? sgA1 : sgB1;
            const int r0 = base0 + c * 16;
            const int r1 = r0 + 8;
            if (lm == 0) {
                out[3 * r0 + 0] = sigm(D5[0]);
                out[3 * r0 + 1] = sigm(D5[1]);
                out[3 * r1 + 0] = sigm(D5[2]);
                out[3 * r1 + 1] = sigm(D5[3]);
                out[3 * NPTS + r0] = sg0;
                out[3 * NPTS + r1] = sg1;
            } else if (lm == 1) {
                out[3 * r0 + 2] = sigm(D5[0]);
                out[3 * r1 + 2] = sigm(D5[2]);
            }
        }
    }
}

extern "C" void kernel_launch(void* const* d_in, const int* in_sizes, int n_in,
                              void* d_out, int out_size) {
    const float* x      = (const float*)d_in[0];
    const float* pxy    = (const float*)d_in[2];
    const float* pxz    = (const float*)d_in[3];
    const float* pyz    = (const float*)d_in[4];
    const float* center = (const float*)d_in[5];
    const float* scale  = (const float*)d_in[6];
    const float* w1     = (const float*)d_in[7];
    const float* w2     = (const float*)d_in[8];
    const float* w3     = (const float*)d_in[9];
    const float* w4     = (const float*)d_in[10];
    const float* w5     = (const float*)d_in[11];

    cudaFuncSetAttribute(nerf_mma, cudaFuncAttributeMaxDynamicSharedMemorySize, SMEM_TOTAL);

    dim3 tb(32, 32), tg(8, 256, 3);
    transpose_kernel<<<tg, tb>>>(pxy, pxz, pyz);
    nerf_mma<<<NBLK, TPB, SMEM_TOTAL>>>(x, center, scale, w1, w2, w3, w4, w5, (float*)d_out);
}

// round 17
// speedup vs baseline: 1.1315x; 1.0061x over previous
#include <cuda_runtime.h>
#include <cuda_fp16.h>

typedef unsigned int u32;

static constexpr int NPTS  = 1048576;
static constexpr int TPB   = 256;
static constexpr int TILE_PTS = 256;
static constexpr int TILES = NPTS / TILE_PTS;  // 4096
static constexpr int NBLK  = 296;              // 2 CTAs/SM * 148 SMs

// fp16 staging: per warp, 3 planes x 32 rows x 20 u32 (16 data + 4 pad)
static constexpr int SF_U32_PER_WARP = 3 * 32 * 20;            // 1920
static constexpr int SF_BYTES = 8 * SF_U32_PER_WARP * 4;       // 61440
static constexpr int NPAIR = 50;                               // 50 uint4 fragment pairs
static constexpr int SWF_OFF = SF_BYTES;                       // 61440
static constexpr int SMEM_TOTAL = SWF_OFF + NPAIR * 512;       // 87040

// fragment pair map (original idx -> pair = idx>>1, sub = idx&1):
//  W1  (96,64): idx 0..47   -> pairs 0..23   (kt*4 + nt/2)
//  W3' (16,64): idx 48..55  -> pairs 24..27
//  W4  (64,64): idx 56..87  -> pairs 28..43
//  W5' (64,8):  idx 88..91  -> pairs 44..45
//  W2  (64,16): idx 92..99  -> pairs 46..49

// ---------------- planes as fp16 u-paired cells ----------------
__device__ __half g2[3 * 256 * 256 * 64];

__global__ void transpose_kernel(const float* __restrict__ pxy,
                                 const float* __restrict__ pxz,
                                 const float* __restrict__ pyz) {
    __shared__ float tile[32][33];
    const float* src = blockIdx.z == 0 ? pxy : (blockIdx.z == 1 ? pxz : pyz);
    const int x0 = blockIdx.x * 32;
    const int y  = blockIdx.y;
    const int tx = threadIdx.x;
    const int ty = threadIdx.y;

    tile[ty][tx] = src[ty * 65536 + y * 256 + x0 + tx];
    if (tx == 0) {
        const int ulast = min(x0 + 32, 255);
        tile[ty][32] = src[ty * 65536 + y * 256 + ulast];
    }
    __syncthreads();

    const float a = tile[tx][ty];
    const float b = tile[tx][ty + 1];
    half2 hp = __floats2half2_rn(a, b);
    u32* g2u = (u32*)g2;
    g2u[((u32)blockIdx.z * 65536u + (u32)(y * 256 + x0 + ty)) * 32u + (u32)tx] =
        *reinterpret_cast<u32*>(&hp);
}

// ---------------- helpers ----------------
__device__ __forceinline__ u32 hi2(float a, float b) {
    half2 h = __floats2half2_rn(a, b);
    return *reinterpret_cast<u32*>(&h);
}
__device__ __forceinline__ u32 hi2_relu(float a, float b) {
    half2 h = __floats2half2_rn(a, b);
    half2 z = __float2half2_rn(0.f);
    h = __hmax2(h, z);
    return *reinterpret_cast<u32*>(&h);
}

__device__ __forceinline__ void mma16(float* d, const u32* a, u32 b0, u32 b1) {
    asm volatile("mma.sync.aligned.m16n8k16.row.col.f32.f16.f16.f32 "
                 "{%0,%1,%2,%3}, {%4,%5,%6,%7}, {%8,%9}, {%0,%1,%2,%3};"
                 : "+f"(d[0]), "+f"(d[1]), "+f"(d[2]), "+f"(d[3])
                 : "r"(a[0]), "r"(a[1]), "r"(a[2]), "r"(a[3]), "r"(b0), "r"(b1));
}

__device__ __forceinline__ void build_hi_relu(const float* s0, const float* s1, u32* ah) {
    ah[0] = hi2_relu(s0[0], s0[1]);
    ah[1] = hi2_relu(s0[2], s0[3]);
    ah[2] = hi2_relu(s1[0], s1[1]);
    ah[3] = hi2_relu(s1[2], s1[3]);
}
__device__ __forceinline__ void build_hi(const float* s0, const float* s1, u32* ah) {
    ah[0] = hi2(s0[0], s0[1]);
    ah[1] = hi2(s0[2], s0[3]);
    ah[2] = hi2(s1[0], s1[1]);
    ah[3] = hi2(s1[2], s1[3]);
}

__device__ __forceinline__ float sigm(float x) { return 1.f / (1.f + __expf(-x)); }

__global__ __launch_bounds__(TPB, 2)
void nerf_mma(const float* __restrict__ xin,
              const float* __restrict__ center,
              const float* __restrict__ scale,
              const float* __restrict__ w1,
              const float* __restrict__ w2,
              const float* __restrict__ w3,
              const float* __restrict__ w4,
              const float* __restrict__ w5,
              float* __restrict__ out) {
    extern __shared__ __align__(16) char smem[];
    u32*   sf16 = (u32*)smem;
    uint2* swfh = (uint2*)(smem + SWF_OFF);   // half-granular write view
    const uint4* swf4 = (const uint4*)(smem + SWF_OFF);  // paired read view

    const int tid  = threadIdx.x;
    const int wid  = tid >> 5;
    const int lane = tid & 31;
    const int g  = lane >> 2;        // fragment row group
    const int t2 = (lane & 3) * 2;   // fragment col pair

    // ---- build weight fragments (hi-only; stored as uint4 pairs) ----
    for (int f = wid; f < 100; f += 8) {
        float v0, v1, v2, v3;
        int idx;
        if (f < 48) {
            int kt = f >> 3, nt = f & 7;
            int ka = kt * 16 + t2, n = nt * 8 + g;
            v0 = w1[ka * 64 + n];       v1 = w1[(ka + 1) * 64 + n];
            v2 = w1[(ka + 8) * 64 + n]; v3 = w1[(ka + 9) * 64 + n];
            idx = f;
        } else if (f < 56) {
            int q = f - 48, kt = q >> 1, nt = q & 1;
            int ka = kt * 16 + t2, n = nt * 8 + g;
            v0 = w2[ka * 16 + n];       v1 = w2[(ka + 1) * 16 + n];
            v2 = w2[(ka + 8) * 16 + n]; v3 = w2[(ka + 9) * 16 + n];
            idx = 92 + q;
        } else if (f < 64) {
            int nt = f - 56;
            int ka = t2, n = nt * 8 + g;
            v0 = (ka == 0) ? 0.f : w3[(ka - 1) * 64 + n];
            v1 = w3[ka * 64 + n];
            v2 = w3[(ka + 7) * 64 + n];
            v3 = w3[(ka + 8) * 64 + n];
            idx = 48 + nt;
        } else if (f < 96) {
            int q = f - 64, kt = q >> 3, nt = q & 7;
            int ka = kt * 16 + t2, n = nt * 8 + g;
            v0 = w4[ka * 64 + n];       v1 = w4[(ka + 1) * 64 + n];
            v2 = w4[(ka + 8) * 64 + n]; v3 = w4[(ka + 9) * 64 + n];
            idx = 56 + q;
        } else {
            int kt = f - 96;
            int ka = kt * 16 + t2, n = g;
            v0 = (n < 3) ? w5[ka * 3 + n] : 0.f;
            v1 = (n < 3) ? w5[(ka + 1) * 3 + n] : 0.f;
            v2 = (n < 3) ? w5[(ka + 8) * 3 + n] : 0.f;
            v3 = (n < 3) ? w5[(ka + 9) * 3 + n] : 0.f;
            idx = 88 + kt;
        }
        uint2 q2;
        q2.x = hi2(v0, v1);
        q2.y = hi2(v2, v3);
        // pair layout: uint2 slot = pair*64 + lane*2 + sub
        swfh[(idx >> 1) * 64 + lane * 2 + (idx & 1)] = q2;
    }
    __syncthreads();

    const float c0 = center[0], c1 = center[1], c2 = center[2];
    const float s0 = scale[0],  s1 = scale[1],  s2 = scale[2];
    const int jj = lane & 7;     // channel chunk (4 channels)
    const int p4 = lane >> 3;    // point-in-group
    const int wb = wid * SF_U32_PER_WARP;   // staging base (u32)
    const int cb = lane & 3;     // u32 col within k-tile
    const half2 one2 = __float2half2_rn(1.f);

    for (int tile = blockIdx.x; tile < TILES; tile += gridDim.x) {
        const int pid = tile * TILE_PTS + wid * 32 + lane;
        const float px = xin[3 * pid + 0];
        const float py = xin[3 * pid + 1];
        const float pz = xin[3 * pid + 2];

        float vx = fminf(fmaxf((px - c0) / s0 + 0.5f, 0.f), 1.f) * 255.f;
        float vy = fminf(fmaxf((py - c1) / s1 + 0.5f, 0.f), 1.f) * 255.f;
        float vz = fminf(fmaxf((pz - c2) / s2 + 0.5f, 0.f), 1.f) * 255.f;
        float flx = floorf(vx), fly = floorf(vy), flz = floorf(vz);
        float fx = vx - flx, fy = vy - fly, fz = vz - flz;
        int x0i = (int)flx;
        int y0i = (int)fly, y1i = min(y0i + 1, 255);
        int z0i = (int)flz, z1i = min(z0i + 1, 255);

        u32 gm[3];
        float gfu[3], gfv[3];
        {
            const float fus[3] = {fx, fx, fy};
            const float fvs[3] = {fy, fz, fz};
            const int u0s[3] = {x0i, x0i, y0i};
            const int v0s[3] = {y0i, z0i, z0i}, v1s[3] = {y1i, z1i, z1i};
#pragma unroll
            for (int q = 0; q < 3; q++) {
                u32 base = ((u32)q * 65536u + (u32)(v0s[q] * 256 + u0s[q])) * 64u;
                gm[q] = base | ((v1s[q] > v0s[q]) ? (1u << 31) : 0u);
                gfu[q] = fus[q];
                gfv[q] = fvs[q];
            }
        }

        // ---- single-phase gather: half2 lerp + PRMT pack ----
        __syncwarp();
#pragma unroll
        for (int q = 0; q < 3; q++) {
#pragma unroll
            for (int gq = 0; gq < 8; gq++) {
                const int src = gq * 4 + p4;
                u32 meta = __shfl_sync(0xffffffffu, gm[q], src);
                float fu = __shfl_sync(0xffffffffu, gfu[q], src);
                float fv = __shfl_sync(0xffffffffu, gfv[q], src);
                const __half* cell = g2 + (meta & 0x00FFFFFFu) + (u32)(jj * 8);
                u32 dv = (meta >> 31) * 16384u;
                float4 rv0 = *(const float4*)cell;
                float4 rv1 = *(const float4*)(cell + dv);
                const half2* h0 = (const half2*)&rv0;
                const half2* h1 = (const half2*)&rv1;
                const half2 fv2  = __float2half2_rn(fv);
                const half2 wu1h = __float2half2_rn(fu);
                const half2 wu0h = __hsub2(one2, wu1h);
                u32 hv[4];
#pragma unroll
                for (int i = 0; i < 4; i++) {
                    half2 t = __hfma2(__hsub2(h1[i], h0[i]), fv2, h0[i]);
                    hv[i] = *reinterpret_cast<u32*>(&t);
                }
                u32 lo0 = __byte_perm(hv[0], hv[1], 0x5410);
                u32 hi0 = __byte_perm(hv[0], hv[1], 0x7632);
                u32 lo1 = __byte_perm(hv[2], hv[3], 0x5410);
                u32 hi1 = __byte_perm(hv[2], hv[3], 0x7632);
                half2 r0 = __hfma2(*reinterpret_cast<half2*>(&hi0), wu1h,
                                   __hmul2(*reinterpret_cast<half2*>(&lo0), wu0h));
                half2 r1 = __hfma2(*reinterpret_cast<half2*>(&hi1), wu1h,
                                   __hmul2(*reinterpret_cast<half2*>(&lo1), wu0h));
                uint2 hp;
                hp.x = *reinterpret_cast<u32*>(&r0);
                hp.y = *reinterpret_cast<u32*>(&r1);
                *(uint2*)&sf16[wb + q * 640 + (gq * 4 + p4) * 20 + jj * 2] = hp;
            }
        }
        __syncwarp();

        // ---- L1 paired: A exact fp16, B pairs via LDS.128 ----
        float D1a[8][4], D1b[8][4];
#pragma unroll
        for (int n = 0; n < 8; n++)
#pragma unroll
            for (int q = 0; q < 4; q++) { D1a[n][q] = 0.f; D1b[n][q] = 0.f; }
#pragma unroll
        for (int kt = 0; kt < 6; kt++) {
            const int q = kt >> 1, kq = kt & 1;
            const int base = wb + q * 640;
            const int col = kq * 8 + cb;
            u32 A0[4], A1[4];
            A0[0] = sf16[base + g * 20 + col];
            A0[1] = sf16[base + (g + 8) * 20 + col];
            A0[2] = sf16[base + g * 20 + col + 4];
            A0[3] = sf16[base + (g + 8) * 20 + col + 4];
            A1[0] = sf16[base + (16 + g) * 20 + col];
            A1[1] = sf16[base + (24 + g) * 20 + col];
            A1[2] = sf16[base + (16 + g) * 20 + col + 4];
            A1[3] = sf16[base + (24 + g) * 20 + col + 4];
#pragma unroll
            for (int nt2 = 0; nt2 < 4; nt2++) {
                uint4 B = swf4[(kt * 4 + nt2) * 32 + lane];
                mma16(D1a[2 * nt2],     A0, B.x, B.y);
                mma16(D1a[2 * nt2 + 1], A0, B.z, B.w);
                mma16(D1b[2 * nt2],     A1, B.x, B.y);
                mma16(D1b[2 * nt2 + 1], A1, B.z, B.w);
            }
        }

        // ---- L2 paired (1-term; pairs 46..49) ----
        float D2a[2][4], D2b[2][4];
#pragma unroll
        for (int n = 0; n < 2; n++)
#pragma unroll
            for (int q = 0; q < 4; q++) { D2a[n][q] = 0.f; D2b[n][q] = 0.f; }
#pragma unroll
        for (int kt = 0; kt < 4; kt++) {
            u32 ahA[4], ahB[4];
            build_hi_relu(D1a[2 * kt], D1a[2 * kt + 1], ahA);
            build_hi_relu(D1b[2 * kt], D1b[2 * kt + 1], ahB);
            uint4 B = swf4[(46 + kt) * 32 + lane];
            mma16(D2a[0], ahA, B.x, B.y);
            mma16(D2a[1], ahA, B.z, B.w);
            mma16(D2b[0], ahB, B.x, B.y);
            mma16(D2b[1], ahB, B.z, B.w);
        }
        const float sgA0 = D2a[0][0], sgA1 = D2a[0][2];
        const float sgB0 = D2b[0][0], sgB1 = D2b[0][2];

        // ---- L3 paired (1-term; pairs 24..27) ----
        float D3a[8][4], D3b[8][4];
#pragma unroll
        for (int n = 0; n < 8; n++)
#pragma unroll
            for (int q = 0; q < 4; q++) { D3a[n][q] = 0.f; D3b[n][q] = 0.f; }
        {
            u32 ahA[4], ahB[4];
            build_hi(D2a[0], D2a[1], ahA);
            build_hi(D2b[0], D2b[1], ahB);
#pragma unroll
            for (int nt2 = 0; nt2 < 4; nt2++) {
                uint4 B = swf4[(24 + nt2) * 32 + lane];
                mma16(D3a[2 * nt2],     ahA, B.x, B.y);
                mma16(D3a[2 * nt2 + 1], ahA, B.z, B.w);
                mma16(D3b[2 * nt2],     ahB, B.x, B.y);
                mma16(D3b[2 * nt2 + 1], ahB, B.z, B.w);
            }
        }

        // ---- D3 -> hi-only A4 ----
        u32 A4a[4][4], A4b[4][4];
#pragma unroll
        for (int kt = 0; kt < 4; kt++) {
            build_hi_relu(D3a[2 * kt], D3a[2 * kt + 1], A4a[kt]);
            build_hi_relu(D3b[2 * kt], D3b[2 * kt + 1], A4b[kt]);
        }

        // ---- L4 + L5 paired, 1-term, two n-halves (pairs 28..43, 44..45) ----
        float D5a[4] = {0.f, 0.f, 0.f, 0.f};
        float D5b[4] = {0.f, 0.f, 0.f, 0.f};
#pragma unroll
        for (int half = 0; half < 2; half++) {
            float D4a[4][4], D4b[4][4];
#pragma unroll
            for (int n = 0; n < 4; n++)
#pragma unroll
                for (int q = 0; q < 4; q++) { D4a[n][q] = 0.f; D4b[n][q] = 0.f; }
#pragma unroll
            for (int kt = 0; kt < 4; kt++) {
#pragma unroll
                for (int nt2 = 0; nt2 < 2; nt2++) {
                    uint4 B = swf4[(28 + kt * 4 + half * 2 + nt2) * 32 + lane];
                    mma16(D4a[2 * nt2],     A4a[kt], B.x, B.y);
                    mma16(D4a[2 * nt2 + 1], A4a[kt], B.z, B.w);
                    mma16(D4b[2 * nt2],     A4b[kt], B.x, B.y);
                    mma16(D4b[2 * nt2 + 1], A4b[kt], B.z, B.w);
                }
            }
            {
                uint4 B = swf4[(44 + half) * 32 + lane];
                u32 ah[4];
                build_hi_relu(D4a[0], D4a[1], ah);
                mma16(D5a, ah, B.x, B.y);
                build_hi_relu(D4a[2], D4a[3], ah);
                mma16(D5a, ah, B.z, B.w);
                build_hi_relu(D4b[0], D4b[1], ah);
                mma16(D5b, ah, B.x, B.y);
                build_hi_relu(D4b[2], D4b[3], ah);
                mma16(D5b, ah, B.z, B.w);
            }
        }

        // ---- epilogue ----
        const int lm = lane & 3;
        const int base0 = tile * TILE_PTS + wid * 32 + g;
#pragma unroll
        for (int c = 0; c < 2; c++) {
            const float* D5 = c == 0 ? D5a : D5b;
            const float sg0 = c == 0 ? sgA0 : sgB0;
            const float sg1 = c == 0 ? sgA1 : sgB1;
            const int r0 = base0 + c * 16;
            const int r1 = r0 + 8;
            if (lm == 0) {
                out[3 * r0 + 0] = sigm(D5[0]);
                out[3 * r0 + 1] = sigm(D5[1]);
                out[3 * r1 + 0] = sigm(D5[2]);
                out[3 * r1 + 1] = sigm(D5[3]);
                out[3 * NPTS + r0] = sg0;
                out[3 * NPTS + r1] = sg1;
            } else if (lm == 1) {
                out[3 * r0 + 2] = sigm(D5[0]);
                out[3 * r1 + 2] = sigm(D5[2]);
            }
        }
    }
}

extern "C" void kernel_launch(void* const* d_in, const int* in_sizes, int n_in,
                              void* d_out, int out_size) {
    const float* x      = (const float*)d_in[0];
    const float* pxy    = (const float*)d_in[2];
    const float* pxz    = (const float*)d_in[3];
    const float* pyz    = (const float*)d_in[4];
    const float* center = (const float*)d_in[5];
    const float* scale  = (const float*)d_in[6];
    const float* w1     = (const float*)d_in[7];
    const float* w2     = (const float*)d_in[8];
    const float* w3     = (const float*)d_in[9];
    const float* w4     = (const float*)d_in[10];
    const float* w5     = (const float*)d_in[11];

    cudaFuncSetAttribute(nerf_mma, cudaFuncAttributeMaxDynamicSharedMemorySize, SMEM_TOTAL);

    dim3 tb(32, 32), tg(8, 256, 3);
    transpose_kernel<<<tg, tb>>>(pxy, pxz, pyz);
    nerf_mma<<<NBLK, TPB, SMEM_TOTAL>>>(x, center, scale, w1, w2, w3, w4, w5, (float*)d_out);
}